// round 1
// baseline (speedup 1.0000x reference)
#include <cuda_runtime.h>
#include <cuda_bf16.h>
#include <cstdint>

// Problem constants
#define BB 2
#define SS 2048
#define DD 1024
#define HH 16
#define HD 64
#define NTOK (BB * SS)          // 4096
#define D3  (3 * DD)            // 3072
#define QT  (SS / 64)           // 32 q-tiles per (b,h)

// Scratch (device globals: allocation-free, graph-capture safe)
__device__ float g_qkv[(size_t)NTOK * D3];    // [4096, 3072]
__device__ float g_attn[(size_t)NTOK * DD];   // [4096, 1024]

// ---------------------------------------------------------------------------
// SGEMM: C[M,N] = A[M,K] @ B[K,N] + bias[N]   (all row-major, dims % tile == 0)
// 128x128 block tile, BK=16, 256 threads, 8x8 microtile
// ---------------------------------------------------------------------------
__global__ __launch_bounds__(256) void sgemm_bias_kernel(
    int M, int N, int K,
    const float* __restrict__ A,
    const float* __restrict__ B,
    const float* __restrict__ bias,
    float* __restrict__ C)
{
    constexpr int BM = 128, BN = 128, BK = 16, TM = 8, TN = 8;
    __shared__ float As[BK * BM];   // transposed: As[k][m]
    __shared__ float Bs[BK * BN];   // Bs[k][n]

    const int tid = threadIdx.x;
    const int tx = tid & 15;        // 0..15 -> N
    const int ty = tid >> 4;        // 0..15 -> M
    const int brow = blockIdx.y * BM;
    const int bcol = blockIdx.x * BN;

    float acc[TM][TN];
    #pragma unroll
    for (int i = 0; i < TM; i++)
        #pragma unroll
        for (int j = 0; j < TN; j++) acc[i][j] = 0.f;

    for (int k0 = 0; k0 < K; k0 += BK) {
        // Load A tile (BM x BK = 512 float4) and B tile (BK x BN = 512 float4)
        #pragma unroll
        for (int i = 0; i < 2; i++) {
            int f = tid + i * 256;
            int ar = f >> 2;              // 0..127
            int ac = (f & 3) << 2;        // 0,4,8,12
            float4 a = *(const float4*)(A + (size_t)(brow + ar) * K + k0 + ac);
            As[(ac + 0) * BM + ar] = a.x;
            As[(ac + 1) * BM + ar] = a.y;
            As[(ac + 2) * BM + ar] = a.z;
            As[(ac + 3) * BM + ar] = a.w;

            int br = f >> 5;              // 0..15
            int bc = (f & 31) << 2;       // 0..124
            *(float4*)(Bs + br * BN + bc) =
                *(const float4*)(B + (size_t)(k0 + br) * N + bcol + bc);
        }
        __syncthreads();

        #pragma unroll
        for (int k = 0; k < BK; k++) {
            float rm[TM], rn[TN];
            #pragma unroll
            for (int i = 0; i < TM; i += 4)
                *(float4*)&rm[i] = *(const float4*)(As + k * BM + ty * TM + i);
            #pragma unroll
            for (int j = 0; j < TN; j += 4)
                *(float4*)&rn[j] = *(const float4*)(Bs + k * BN + tx * TN + j);
            #pragma unroll
            for (int i = 0; i < TM; i++)
                #pragma unroll
                for (int j = 0; j < TN; j++)
                    acc[i][j] = fmaf(rm[i], rn[j], acc[i][j]);
        }
        __syncthreads();
    }

    // Epilogue: add bias, vectorized store
    #pragma unroll
    for (int i = 0; i < TM; i++) {
        int row = brow + ty * TM + i;
        #pragma unroll
        for (int j = 0; j < TN; j += 4) {
            int col = bcol + tx * TN + j;
            float4 o;
            o.x = acc[i][j + 0] + bias[col + 0];
            o.y = acc[i][j + 1] + bias[col + 1];
            o.z = acc[i][j + 2] + bias[col + 2];
            o.w = acc[i][j + 3] + bias[col + 3];
            *(float4*)(C + (size_t)row * N + col) = o;
        }
    }
}

// ---------------------------------------------------------------------------
// Causal flash attention, fp32.
// One block = 64 query rows of one (b,h). 64 threads, thread t owns row t.
// K/V tiles (64x64) staged in smem, read via broadcast float4 (4 FMA / LDS.128).
// S scratch stored transposed (Ssh[j*64 + tid]) -> conflict-free.
// grid: (32 q-tiles, 32 b*h); heavy tiles first via qt = 31 - blockIdx.x.
// ---------------------------------------------------------------------------
__global__ __launch_bounds__(64) void attn_kernel(
    const float* __restrict__ qkv, float* __restrict__ out)
{
    const int qt = (QT - 1) - blockIdx.x;     // heavy blocks scheduled first
    const int bh = blockIdx.y;
    const int b = bh >> 4;
    const int h = bh & 15;
    const int tid = threadIdx.x;              // 0..63

    __shared__ float Ks[64 * 64];
    __shared__ float Vs[64 * 64];
    __shared__ float Ssh[64 * 64];            // transposed: [j][row]

    const int qg = qt * 64 + tid;
    const float* qptr = qkv + (size_t)(b * SS + qg) * D3 + h * HD;

    // q pre-scaled by 1/sqrt(HD)
    float4 q4[16];
    #pragma unroll
    for (int i = 0; i < 16; i++) {
        float4 v = ((const float4*)qptr)[i];
        v.x *= 0.125f; v.y *= 0.125f; v.z *= 0.125f; v.w *= 0.125f;
        q4[i] = v;
    }

    float acc[64];
    #pragma unroll
    for (int d = 0; d < 64; d++) acc[d] = 0.f;
    float m = -1e30f, l = 0.f;

    for (int kt = 0; kt <= qt; ++kt) {
        // Cooperative K/V tile load: 4 rows x 16 float4-lanes per pass
        const float* kbase = qkv + (size_t)(b * SS + kt * 64) * D3 + DD + h * HD;
        const float* vbase = kbase + DD;
        {
            int c4 = tid & 15;
            int r0 = tid >> 4;
            #pragma unroll
            for (int i = 0; i < 16; i++) {
                int row = r0 + i * 4;
                ((float4*)Ks)[row * 16 + c4] =
                    ((const float4*)(kbase + (size_t)row * D3))[c4];
                ((float4*)Vs)[row * 16 + c4] =
                    ((const float4*)(vbase + (size_t)row * D3))[c4];
            }
        }
        __syncthreads();

        // Phase A: scores for 64 keys, track running max
        float mt = m;
        const bool diag = (kt == qt);
        for (int j = 0; j < 64; j++) {
            float s0 = 0.f, s1 = 0.f, s2 = 0.f, s3 = 0.f;
            #pragma unroll
            for (int d4 = 0; d4 < 16; d4++) {
                float4 kk = ((const float4*)Ks)[j * 16 + d4];
                s0 = fmaf(q4[d4].x, kk.x, s0);
                s1 = fmaf(q4[d4].y, kk.y, s1);
                s2 = fmaf(q4[d4].z, kk.z, s2);
                s3 = fmaf(q4[d4].w, kk.w, s3);
            }
            float s = (s0 + s1) + (s2 + s3);
            if (diag && j > tid) s = -1e30f;
            Ssh[j * 64 + tid] = s;
            mt = fmaxf(mt, s);
        }

        // Rescale running state once per tile
        float corr = __expf(m - mt);
        m = mt;
        l *= corr;
        #pragma unroll
        for (int d = 0; d < 64; d++) acc[d] *= corr;

        // Phase B: softmax weights + PV accumulation
        for (int j = 0; j < 64; j++) {
            float p = __expf(Ssh[j * 64 + tid] - m);
            l += p;
            #pragma unroll
            for (int d4 = 0; d4 < 16; d4++) {
                float4 vv = ((const float4*)Vs)[j * 16 + d4];
                acc[4 * d4 + 0] = fmaf(p, vv.x, acc[4 * d4 + 0]);
                acc[4 * d4 + 1] = fmaf(p, vv.y, acc[4 * d4 + 1]);
                acc[4 * d4 + 2] = fmaf(p, vv.z, acc[4 * d4 + 2]);
                acc[4 * d4 + 3] = fmaf(p, vv.w, acc[4 * d4 + 3]);
            }
        }
        __syncthreads();
    }

    // Normalize and write out (merged-head layout [tok, D])
    float inv = 1.f / l;
    float* optr = out + (size_t)(b * SS + qg) * DD + h * HD;
    #pragma unroll
    for (int d4 = 0; d4 < 16; d4++) {
        float4 o;
        o.x = acc[4 * d4 + 0] * inv;
        o.y = acc[4 * d4 + 1] * inv;
        o.z = acc[4 * d4 + 2] * inv;
        o.w = acc[4 * d4 + 3] * inv;
        ((float4*)optr)[d4] = o;
    }
}

// ---------------------------------------------------------------------------
// Launch
// ---------------------------------------------------------------------------
extern "C" void kernel_launch(void* const* d_in, const int* in_sizes, int n_in,
                              void* d_out, int out_size)
{
    const float* hidden = (const float*)d_in[0];   // [B,S,D]
    const float* wqkv   = (const float*)d_in[1];   // [D, 3D]
    const float* bqkv   = (const float*)d_in[2];   // [3D]
    const float* wproj  = (const float*)d_in[3];   // [D, D]
    const float* bproj  = (const float*)d_in[4];   // [D]
    float* out = (float*)d_out;                    // [B,S,D]

    void *qkv_p = nullptr, *attn_p = nullptr;
    cudaGetSymbolAddress(&qkv_p, g_qkv);
    cudaGetSymbolAddress(&attn_p, g_attn);
    float* qkv  = (float*)qkv_p;
    float* attn = (float*)attn_p;

    // 1) QKV projection: [4096,1024] @ [1024,3072] + b
    {
        dim3 grid(D3 / 128, NTOK / 128);   // 24 x 32
        sgemm_bias_kernel<<<grid, 256>>>(NTOK, D3, DD, hidden, wqkv, bqkv, qkv);
    }

    // 2) Causal flash attention per (b,h)
    {
        dim3 grid(QT, BB * HH);            // 32 x 32
        attn_kernel<<<grid, 64>>>(qkv, attn);
    }

    // 3) Output projection: [4096,1024] @ [1024,1024] + b
    {
        dim3 grid(DD / 128, NTOK / 128);   // 8 x 32
        sgemm_bias_kernel<<<grid, 256>>>(NTOK, DD, DD, attn, wproj, bproj, out);
    }
}

// round 2
// speedup vs baseline: 1.1132x; 1.1132x over previous
#include <cuda_runtime.h>
#include <cuda_bf16.h>
#include <mma.h>
#include <cstdint>

using namespace nvcuda;

// Problem constants
#define BB 2
#define SS 2048
#define DD 1024
#define HH 16
#define HD 64
#define NTOK (BB * SS)          // 4096
#define D3  (3 * DD)            // 3072
#define QT  (SS / 64)           // 32 q-tiles per (b,h)

// Scratch (device globals: allocation-free, graph-capture safe)
__device__ float g_qkv[(size_t)NTOK * D3];    // [4096, 3072]
__device__ float g_attn[(size_t)NTOK * DD];   // [4096, 1024]

// ---------------------------------------------------------------------------
// TF32 tensor-core GEMM: C[M,N] = A[M,K] @ B[K,N] + bias[N]
// BM=128, BN=128, BK=32; 256 threads = 8 warps (4 M-strips x 2 N-strips);
// each warp computes 32x64 via 2x4 wmma 16x16x8 tf32 fragments.
// Bias is preloaded into the accumulator via a replicated 16-row smem tile.
// ---------------------------------------------------------------------------
__global__ __launch_bounds__(256) void tf32_gemm_bias_kernel(
    int M, int N, int K,
    const float* __restrict__ A,
    const float* __restrict__ B,
    const float* __restrict__ bias,
    float* __restrict__ C)
{
    constexpr int BM = 128, BN = 128, BK = 32;
    constexpr int BKp = 40;    // A row stride (floats): 160B -> 32B-aligned rows
    constexpr int BNp = 136;   // B row stride (floats): 544B -> 32B-aligned rows

    __shared__ float As[BM * BKp];     // [128][40]  row-major A tile
    __shared__ float Bs[BK * BNp];     // [32][136]  row-major B tile
    __shared__ float BiasS[16 * BNp];  // bias replicated across 16 rows

    const int tid = threadIdx.x;
    const int wid = tid >> 5;
    const int wm = wid & 3;            // 0..3 -> M strip (32 rows)
    const int wn = wid >> 2;           // 0..1 -> N strip (64 cols)
    const int brow = blockIdx.y * BM;
    const int bcol = blockIdx.x * BN;

    // Fill replicated bias tile
    if (tid < BN) {
        float bv = bias[bcol + tid];
        #pragma unroll
        for (int r = 0; r < 16; r++) BiasS[r * BNp + tid] = bv;
    }
    __syncthreads();

    // Accumulators initialized with bias (all 16 rows of BiasS identical)
    wmma::fragment<wmma::accumulator, 16, 16, 8, float> acc[2][4];
    #pragma unroll
    for (int i = 0; i < 2; i++)
        #pragma unroll
        for (int j = 0; j < 4; j++)
            wmma::load_matrix_sync(acc[i][j], BiasS + wn * 64 + j * 16, BNp,
                                   wmma::mem_row_major);
    __syncthreads();

    for (int k0 = 0; k0 < K; k0 += BK) {
        // Load A tile: 128x32 floats = 1024 float4, 4 per thread
        #pragma unroll
        for (int i = 0; i < 4; i++) {
            int f = tid + i * 256;
            int ar = f >> 3;
            int ac = (f & 7) << 2;
            *(float4*)(As + ar * BKp + ac) =
                *(const float4*)(A + (size_t)(brow + ar) * K + k0 + ac);
        }
        // Load B tile: 32x128 floats = 1024 float4, 4 per thread
        #pragma unroll
        for (int i = 0; i < 4; i++) {
            int f = tid + i * 256;
            int br = f >> 5;
            int bc = (f & 31) << 2;
            *(float4*)(Bs + br * BNp + bc) =
                *(const float4*)(B + (size_t)(k0 + br) * N + bcol + bc);
        }
        __syncthreads();

        #pragma unroll
        for (int kk = 0; kk < BK; kk += 8) {
            wmma::fragment<wmma::matrix_a, 16, 16, 8, wmma::precision::tf32,
                           wmma::row_major> af[2];
            wmma::fragment<wmma::matrix_b, 16, 16, 8, wmma::precision::tf32,
                           wmma::row_major> bf[4];
            #pragma unroll
            for (int i = 0; i < 2; i++) {
                wmma::load_matrix_sync(af[i],
                    As + (wm * 32 + i * 16) * BKp + kk, BKp);
                #pragma unroll
                for (int e = 0; e < af[i].num_elements; e++)
                    af[i].x[e] = wmma::__float_to_tf32(af[i].x[e]);
            }
            #pragma unroll
            for (int j = 0; j < 4; j++) {
                wmma::load_matrix_sync(bf[j],
                    Bs + kk * BNp + wn * 64 + j * 16, BNp);
                #pragma unroll
                for (int e = 0; e < bf[j].num_elements; e++)
                    bf[j].x[e] = wmma::__float_to_tf32(bf[j].x[e]);
            }
            #pragma unroll
            for (int i = 0; i < 2; i++)
                #pragma unroll
                for (int j = 0; j < 4; j++)
                    wmma::mma_sync(acc[i][j], af[i], bf[j], acc[i][j]);
        }
        __syncthreads();
    }

    // Store
    #pragma unroll
    for (int i = 0; i < 2; i++) {
        int row = brow + wm * 32 + i * 16;
        #pragma unroll
        for (int j = 0; j < 4; j++) {
            int col = bcol + wn * 64 + j * 16;
            wmma::store_matrix_sync(C + (size_t)row * N + col, acc[i][j], N,
                                    wmma::mem_row_major);
        }
    }
}

// ---------------------------------------------------------------------------
// Causal flash attention, fp32 (unchanged from round 1).
// ---------------------------------------------------------------------------
__global__ __launch_bounds__(64) void attn_kernel(
    const float* __restrict__ qkv, float* __restrict__ out)
{
    const int qt = (QT - 1) - blockIdx.x;     // heavy blocks scheduled first
    const int bh = blockIdx.y;
    const int b = bh >> 4;
    const int h = bh & 15;
    const int tid = threadIdx.x;              // 0..63

    __shared__ float Ks[64 * 64];
    __shared__ float Vs[64 * 64];
    __shared__ float Ssh[64 * 64];            // transposed: [j][row]

    const int qg = qt * 64 + tid;
    const float* qptr = qkv + (size_t)(b * SS + qg) * D3 + h * HD;

    // q pre-scaled by 1/sqrt(HD)
    float4 q4[16];
    #pragma unroll
    for (int i = 0; i < 16; i++) {
        float4 v = ((const float4*)qptr)[i];
        v.x *= 0.125f; v.y *= 0.125f; v.z *= 0.125f; v.w *= 0.125f;
        q4[i] = v;
    }

    float acc[64];
    #pragma unroll
    for (int d = 0; d < 64; d++) acc[d] = 0.f;
    float m = -1e30f, l = 0.f;

    for (int kt = 0; kt <= qt; ++kt) {
        const float* kbase = qkv + (size_t)(b * SS + kt * 64) * D3 + DD + h * HD;
        const float* vbase = kbase + DD;
        {
            int c4 = tid & 15;
            int r0 = tid >> 4;
            #pragma unroll
            for (int i = 0; i < 16; i++) {
                int row = r0 + i * 4;
                ((float4*)Ks)[row * 16 + c4] =
                    ((const float4*)(kbase + (size_t)row * D3))[c4];
                ((float4*)Vs)[row * 16 + c4] =
                    ((const float4*)(vbase + (size_t)row * D3))[c4];
            }
        }
        __syncthreads();

        // Phase A: scores for 64 keys, track running max
        float mt = m;
        const bool diag = (kt == qt);
        for (int j = 0; j < 64; j++) {
            float s0 = 0.f, s1 = 0.f, s2 = 0.f, s3 = 0.f;
            #pragma unroll
            for (int d4 = 0; d4 < 16; d4++) {
                float4 kk = ((const float4*)Ks)[j * 16 + d4];
                s0 = fmaf(q4[d4].x, kk.x, s0);
                s1 = fmaf(q4[d4].y, kk.y, s1);
                s2 = fmaf(q4[d4].z, kk.z, s2);
                s3 = fmaf(q4[d4].w, kk.w, s3);
            }
            float s = (s0 + s1) + (s2 + s3);
            if (diag && j > tid) s = -1e30f;
            Ssh[j * 64 + tid] = s;
            mt = fmaxf(mt, s);
        }

        float corr = __expf(m - mt);
        m = mt;
        l *= corr;
        #pragma unroll
        for (int d = 0; d < 64; d++) acc[d] *= corr;

        // Phase B: softmax weights + PV accumulation
        for (int j = 0; j < 64; j++) {
            float p = __expf(Ssh[j * 64 + tid] - m);
            l += p;
            #pragma unroll
            for (int d4 = 0; d4 < 16; d4++) {
                float4 vv = ((const float4*)Vs)[j * 16 + d4];
                acc[4 * d4 + 0] = fmaf(p, vv.x, acc[4 * d4 + 0]);
                acc[4 * d4 + 1] = fmaf(p, vv.y, acc[4 * d4 + 1]);
                acc[4 * d4 + 2] = fmaf(p, vv.z, acc[4 * d4 + 2]);
                acc[4 * d4 + 3] = fmaf(p, vv.w, acc[4 * d4 + 3]);
            }
        }
        __syncthreads();
    }

    float inv = 1.f / l;
    float* optr = out + (size_t)(b * SS + qg) * DD + h * HD;
    #pragma unroll
    for (int d4 = 0; d4 < 16; d4++) {
        float4 o;
        o.x = acc[4 * d4 + 0] * inv;
        o.y = acc[4 * d4 + 1] * inv;
        o.z = acc[4 * d4 + 2] * inv;
        o.w = acc[4 * d4 + 3] * inv;
        ((float4*)optr)[d4] = o;
    }
}

// ---------------------------------------------------------------------------
// Launch
// ---------------------------------------------------------------------------
extern "C" void kernel_launch(void* const* d_in, const int* in_sizes, int n_in,
                              void* d_out, int out_size)
{
    const float* hidden = (const float*)d_in[0];   // [B,S,D]
    const float* wqkv   = (const float*)d_in[1];   // [D, 3D]
    const float* bqkv   = (const float*)d_in[2];   // [3D]
    const float* wproj  = (const float*)d_in[3];   // [D, D]
    const float* bproj  = (const float*)d_in[4];   // [D]
    float* out = (float*)d_out;                    // [B,S,D]

    void *qkv_p = nullptr, *attn_p = nullptr;
    cudaGetSymbolAddress(&qkv_p, g_qkv);
    cudaGetSymbolAddress(&attn_p, g_attn);
    float* qkv  = (float*)qkv_p;
    float* attn = (float*)attn_p;

    // 1) QKV projection: [4096,1024] @ [1024,3072] + b   (tf32 tensor cores)
    {
        dim3 grid(D3 / 128, NTOK / 128);   // 24 x 32
        tf32_gemm_bias_kernel<<<grid, 256>>>(NTOK, D3, DD, hidden, wqkv, bqkv, qkv);
    }

    // 2) Causal flash attention per (b,h)
    {
        dim3 grid(QT, BB * HH);            // 32 x 32
        attn_kernel<<<grid, 64>>>(qkv, attn);
    }

    // 3) Output projection: [4096,1024] @ [1024,1024] + b  (tf32 tensor cores)
    {
        dim3 grid(DD / 128, NTOK / 128);   // 8 x 32
        tf32_gemm_bias_kernel<<<grid, 256>>>(NTOK, DD, DD, attn, wproj, bproj, out);
    }
}

// round 4
// speedup vs baseline: 2.3655x; 2.1250x over previous
#include <cuda_runtime.h>
#include <mma.h>
#include <cstdint>

using namespace nvcuda;

// Problem constants
#define BB 2
#define SS 2048
#define DD 1024
#define HH 16
#define HD 64
#define NTOK (BB * SS)          // 4096
#define D3  (3 * DD)            // 3072
#define QT  (SS / 64)           // 32 q-tiles per (b,h)
#define LOG2E 1.4426950408889634f

// Scratch (device globals: allocation-free, graph-capture safe)
__device__ float g_qkv[(size_t)NTOK * D3];    // [4096, 3072]
__device__ float g_attn[(size_t)NTOK * DD];   // [4096, 1024] (tf32-rounded)
__device__ float g_hid_r[(size_t)NTOK * DD];  // tf32-rounded hidden
__device__ float g_w1_r[(size_t)DD * D3];     // tf32-rounded wqkv
__device__ float g_w2_r[(size_t)DD * DD];     // tf32-rounded wproj

// cvt to tf32 needs a .b32 destination; bit pattern is fp32-layout.
__device__ __forceinline__ float rna_tf32(float x) {
    unsigned u; asm("cvt.rna.tf32.f32 %0, %1;" : "=r"(u) : "f"(x));
    return __uint_as_float(u);
}
__device__ __forceinline__ float ex2(float x) {
    float r; asm("ex2.approx.f32 %0, %1;" : "=f"(r) : "f"(x)); return r;
}
__device__ __forceinline__ void mma_tf32(float c[4], const unsigned a[4],
                                         const unsigned b[2]) {
    asm volatile(
        "mma.sync.aligned.m16n8k8.row.col.f32.tf32.tf32.f32 "
        "{%0,%1,%2,%3}, {%4,%5,%6,%7}, {%8,%9}, {%0,%1,%2,%3};"
        : "+f"(c[0]), "+f"(c[1]), "+f"(c[2]), "+f"(c[3])
        : "r"(a[0]), "r"(a[1]), "r"(a[2]), "r"(a[3]), "r"(b[0]), "r"(b[1]));
}

// ---------------------------------------------------------------------------
// Elementwise round-to-tf32 prepass
// ---------------------------------------------------------------------------
__global__ __launch_bounds__(256) void round_tf32_kernel(
    const float* __restrict__ in, float* __restrict__ out, int n4)
{
    int i = blockIdx.x * blockDim.x + threadIdx.x;
    if (i < n4) {
        float4 v = ((const float4*)in)[i];
        v.x = rna_tf32(v.x); v.y = rna_tf32(v.y);
        v.z = rna_tf32(v.z); v.w = rna_tf32(v.w);
        ((float4*)out)[i] = v;
    }
}

// ---------------------------------------------------------------------------
// TF32 GEMM, cp.async 2-stage pipeline, no in-loop conversions (inputs
// pre-rounded to tf32-representable fp32).
// C[M,N] = A[M,K]@B[K,N] + bias.  BM=BN=128, BK=32, 256 thr, 8 warps.
// smem (floats): As0[128*36]@0, As1@4608, Bs0[32*132]@9216, Bs1@13440,
//                BiasS[16*132]@17664; total 19776 floats = 79104 B.
// ---------------------------------------------------------------------------
#define CPA16(dst, src) \
    asm volatile("cp.async.cg.shared.global [%0], [%1], 16;" :: "r"(dst), "l"(src))

__global__ __launch_bounds__(256, 2) void tf32_gemm_pipe_kernel(
    int M, int N, int K,
    const float* __restrict__ A,
    const float* __restrict__ B,
    const float* __restrict__ bias,
    float* __restrict__ C)
{
    extern __shared__ float sm[];
    float* Asm[2] = { sm, sm + 4608 };
    float* Bsm[2] = { sm + 9216, sm + 13440 };
    float* BiasS = sm + 17664;

    const int tid = threadIdx.x;
    const int wid = tid >> 5;
    const int wm = wid & 3;           // M strip (32 rows)
    const int wn = wid >> 2;          // N strip (64 cols)
    const int brow = blockIdx.y * 128;
    const int bcol = blockIdx.x * 128;

    if (tid < 128) {
        float bv = bias[bcol + tid];
        #pragma unroll
        for (int r = 0; r < 16; r++) BiasS[r * 132 + tid] = bv;
    }
    __syncthreads();

    wmma::fragment<wmma::accumulator, 16, 16, 8, float> acc[2][4];
    #pragma unroll
    for (int i = 0; i < 2; i++)
        #pragma unroll
        for (int j = 0; j < 4; j++)
            wmma::load_matrix_sync(acc[i][j], BiasS + wn * 64 + j * 16, 132,
                                   wmma::mem_row_major);

    auto load_stage = [&](int st, int k0) {
        unsigned ab = (unsigned)__cvta_generic_to_shared(Asm[st]);
        unsigned bb = (unsigned)__cvta_generic_to_shared(Bsm[st]);
        #pragma unroll
        for (int i = 0; i < 4; i++) {
            int f = tid + i * 256;
            int ar = f >> 3, ac = (f & 7) << 2;
            CPA16(ab + (unsigned)(ar * 36 + ac) * 4,
                  A + (size_t)(brow + ar) * K + k0 + ac);
            int br = f >> 5, bc = (f & 31) << 2;
            CPA16(bb + (unsigned)(br * 132 + bc) * 4,
                  B + (size_t)(k0 + br) * N + bcol + bc);
        }
        asm volatile("cp.async.commit_group;");
    };

    load_stage(0, 0);
    asm volatile("cp.async.wait_group 0;");
    __syncthreads();

    int st = 0;
    for (int k0 = 0; k0 < K; k0 += 32) {
        if (k0 + 32 < K) load_stage(st ^ 1, k0 + 32);

        #pragma unroll
        for (int kk = 0; kk < 32; kk += 8) {
            wmma::fragment<wmma::matrix_a, 16, 16, 8, wmma::precision::tf32,
                           wmma::row_major> af[2];
            wmma::fragment<wmma::matrix_b, 16, 16, 8, wmma::precision::tf32,
                           wmma::row_major> bf[4];
            #pragma unroll
            for (int i = 0; i < 2; i++)
                wmma::load_matrix_sync(af[i],
                    Asm[st] + (wm * 32 + i * 16) * 36 + kk, 36);
            #pragma unroll
            for (int j = 0; j < 4; j++)
                wmma::load_matrix_sync(bf[j],
                    Bsm[st] + kk * 132 + wn * 64 + j * 16, 132);
            #pragma unroll
            for (int i = 0; i < 2; i++)
                #pragma unroll
                for (int j = 0; j < 4; j++)
                    wmma::mma_sync(acc[i][j], af[i], bf[j], acc[i][j]);
        }

        if (k0 + 32 < K) {
            asm volatile("cp.async.wait_group 0;");
            __syncthreads();
            st ^= 1;
        }
    }

    #pragma unroll
    for (int i = 0; i < 2; i++) {
        int row = brow + wm * 32 + i * 16;
        #pragma unroll
        for (int j = 0; j < 4; j++) {
            int col = bcol + wn * 64 + j * 16;
            wmma::store_matrix_sync(C + (size_t)row * N + col, acc[i][j], N,
                                    wmma::mem_row_major);
        }
    }
}

// ---------------------------------------------------------------------------
// Tensor-core causal flash attention (tf32 mma.sync m16n8k8).
// Block = 128 thr (4 warps) = 64 q-rows of one (b,h). Warp w owns rows
// [16w,16w+16). Q frags in regs; K,V,P staged in smem (stride 68).
// Online softmax in registers using the documented m16n8k8 fragment layout.
// Writes output pre-rounded to tf32 (feeds proj GEMM).
// smem: Ks[64*68], Vs[64*68], Ps[64*68] = 52224 B.
// ---------------------------------------------------------------------------
__global__ __launch_bounds__(128) void attn_tc_kernel(
    const float* __restrict__ qkv, float* __restrict__ out)
{
    extern __shared__ float sm[];
    float* Ks = sm;
    float* Vs = sm + 64 * 68;
    float* Ps = sm + 2 * 64 * 68;

    const int qt = (QT - 1) - blockIdx.x;     // heavy tiles first
    const int bh = blockIdx.y;
    const int b = bh >> 4, h = bh & 15;
    const int tid = threadIdx.x;
    const int w = tid >> 5, lane = tid & 31;
    const int gid = lane >> 2, tig = lane & 3;

    const int tok0 = b * SS + qt * 64;
    const float* qbase = qkv + (size_t)tok0 * D3 + h * HD;
    const int c4 = tid & 15, r0 = tid >> 4;

    // Stage Q (scaled by 1/8*log2e, tf32-rounded) into Ps
    {
        const float s = 0.125f * LOG2E;
        #pragma unroll
        for (int i = 0; i < 8; i++) {
            int row = r0 + i * 8;
            float4 v = *(const float4*)(qbase + (size_t)row * D3 + c4 * 4);
            v.x = rna_tf32(v.x * s); v.y = rna_tf32(v.y * s);
            v.z = rna_tf32(v.z * s); v.w = rna_tf32(v.w * s);
            *(float4*)(Ps + row * 68 + c4 * 4) = v;
        }
    }
    __syncthreads();

    // Q fragments (A of m16n8k8): 8 k-blocks over d=64
    unsigned qf[8][4];
    const int rr = w * 16 + gid;
    #pragma unroll
    for (int kb = 0; kb < 8; kb++) {
        qf[kb][0] = __float_as_uint(Ps[rr * 68 + kb * 8 + tig]);
        qf[kb][1] = __float_as_uint(Ps[(rr + 8) * 68 + kb * 8 + tig]);
        qf[kb][2] = __float_as_uint(Ps[rr * 68 + kb * 8 + tig + 4]);
        qf[kb][3] = __float_as_uint(Ps[(rr + 8) * 68 + kb * 8 + tig + 4]);
    }

    float oacc[8][4];
    #pragma unroll
    for (int i = 0; i < 8; i++)
        #pragma unroll
        for (int j = 0; j < 4; j++) oacc[i][j] = 0.f;
    float m0 = -1e30f, m1 = -1e30f, l0 = 0.f, l1 = 0.f;

    const float* kvbase = qkv + (size_t)(b * SS) * D3 + DD + h * HD;

    for (int kt = 0; kt <= qt; kt++) {
        // Load + tf32-round K and V tiles
        {
            const float* kb_ = kvbase + (size_t)(kt * 64) * D3;
            #pragma unroll
            for (int i = 0; i < 8; i++) {
                int row = r0 + i * 8;
                float4 kv = *(const float4*)(kb_ + (size_t)row * D3 + c4 * 4);
                kv.x = rna_tf32(kv.x); kv.y = rna_tf32(kv.y);
                kv.z = rna_tf32(kv.z); kv.w = rna_tf32(kv.w);
                *(float4*)(Ks + row * 68 + c4 * 4) = kv;
                float4 vv = *(const float4*)(kb_ + (size_t)row * D3 + DD + c4 * 4);
                vv.x = rna_tf32(vv.x); vv.y = rna_tf32(vv.y);
                vv.z = rna_tf32(vv.z); vv.w = rna_tf32(vv.w);
                *(float4*)(Vs + row * 68 + c4 * 4) = vv;
            }
        }
        __syncthreads();

        // S = Q @ K^T : 8 n-blocks of 8 keys
        float sacc[8][4];
        #pragma unroll
        for (int i = 0; i < 8; i++)
            #pragma unroll
            for (int j = 0; j < 4; j++) sacc[i][j] = 0.f;
        #pragma unroll
        for (int nb = 0; nb < 8; nb++) {
            #pragma unroll
            for (int kb = 0; kb < 8; kb++) {
                unsigned bfr[2];
                bfr[0] = __float_as_uint(Ks[(nb * 8 + gid) * 68 + kb * 8 + tig]);
                bfr[1] = __float_as_uint(Ks[(nb * 8 + gid) * 68 + kb * 8 + tig + 4]);
                mma_tf32(sacc[nb], qf[kb], bfr);
            }
        }

        // Causal mask (diagonal tile only; local coords suffice)
        if (kt == qt) {
            #pragma unroll
            for (int nb = 0; nb < 8; nb++) {
                int c0 = nb * 8 + 2 * tig, c1 = c0 + 1;
                if (c0 > rr)     sacc[nb][0] = -1e30f;
                if (c1 > rr)     sacc[nb][1] = -1e30f;
                if (c0 > rr + 8) sacc[nb][2] = -1e30f;
                if (c1 > rr + 8) sacc[nb][3] = -1e30f;
            }
        }

        // Row max (thread-local over 16 cols, then quad shfl reduce)
        float mt0 = -1e30f, mt1 = -1e30f;
        #pragma unroll
        for (int nb = 0; nb < 8; nb++) {
            mt0 = fmaxf(mt0, fmaxf(sacc[nb][0], sacc[nb][1]));
            mt1 = fmaxf(mt1, fmaxf(sacc[nb][2], sacc[nb][3]));
        }
        mt0 = fmaxf(mt0, __shfl_xor_sync(0xffffffffu, mt0, 1));
        mt0 = fmaxf(mt0, __shfl_xor_sync(0xffffffffu, mt0, 2));
        mt1 = fmaxf(mt1, __shfl_xor_sync(0xffffffffu, mt1, 1));
        mt1 = fmaxf(mt1, __shfl_xor_sync(0xffffffffu, mt1, 2));

        float mn0 = fmaxf(m0, mt0), mn1 = fmaxf(m1, mt1);
        float corr0 = ex2(m0 - mn0), corr1 = ex2(m1 - mn1);
        m0 = mn0; m1 = mn1;

        // P = 2^(S - m), row sums
        float rs0 = 0.f, rs1 = 0.f;
        #pragma unroll
        for (int nb = 0; nb < 8; nb++) {
            sacc[nb][0] = ex2(sacc[nb][0] - m0);
            sacc[nb][1] = ex2(sacc[nb][1] - m0);
            sacc[nb][2] = ex2(sacc[nb][2] - m1);
            sacc[nb][3] = ex2(sacc[nb][3] - m1);
            rs0 += sacc[nb][0] + sacc[nb][1];
            rs1 += sacc[nb][2] + sacc[nb][3];
        }
        rs0 += __shfl_xor_sync(0xffffffffu, rs0, 1);
        rs0 += __shfl_xor_sync(0xffffffffu, rs0, 2);
        rs1 += __shfl_xor_sync(0xffffffffu, rs1, 1);
        rs1 += __shfl_xor_sync(0xffffffffu, rs1, 2);
        l0 = l0 * corr0 + rs0;
        l1 = l1 * corr1 + rs1;

        // Rescale O accumulators
        #pragma unroll
        for (int nb = 0; nb < 8; nb++) {
            oacc[nb][0] *= corr0; oacc[nb][1] *= corr0;
            oacc[nb][2] *= corr1; oacc[nb][3] *= corr1;
        }

        // Store P (tf32-rounded) to own warp strip of Ps
        #pragma unroll
        for (int nb = 0; nb < 8; nb++) {
            float2 p01 = { rna_tf32(sacc[nb][0]), rna_tf32(sacc[nb][1]) };
            *(float2*)(Ps + rr * 68 + nb * 8 + 2 * tig) = p01;
            float2 p23 = { rna_tf32(sacc[nb][2]), rna_tf32(sacc[nb][3]) };
            *(float2*)(Ps + (rr + 8) * 68 + nb * 8 + 2 * tig) = p23;
        }
        __syncwarp();

        // O += P @ V : k-dim = 64 keys (8 steps), n = 64 d-cols (8 blocks)
        #pragma unroll
        for (int kb = 0; kb < 8; kb++) {
            unsigned af[4];
            af[0] = __float_as_uint(Ps[rr * 68 + kb * 8 + tig]);
            af[1] = __float_as_uint(Ps[(rr + 8) * 68 + kb * 8 + tig]);
            af[2] = __float_as_uint(Ps[rr * 68 + kb * 8 + tig + 4]);
            af[3] = __float_as_uint(Ps[(rr + 8) * 68 + kb * 8 + tig + 4]);
            #pragma unroll
            for (int nb = 0; nb < 8; nb++) {
                unsigned bfr[2];
                bfr[0] = __float_as_uint(Vs[(kb * 8 + tig) * 68 + nb * 8 + gid]);
                bfr[1] = __float_as_uint(Vs[(kb * 8 + tig + 4) * 68 + nb * 8 + gid]);
                mma_tf32(oacc[nb], af, bfr);
            }
        }
        __syncthreads();   // everyone done with Ks/Vs before next tile's load
    }

    // Epilogue: normalize, round to tf32 (feeds proj GEMM), store
    float inv0 = 1.f / l0, inv1 = 1.f / l1;
    float* o0 = out + (size_t)(tok0 + rr) * DD + h * HD;
    float* o1 = out + (size_t)(tok0 + rr + 8) * DD + h * HD;
    #pragma unroll
    for (int nb = 0; nb < 8; nb++) {
        float2 a = { rna_tf32(oacc[nb][0] * inv0), rna_tf32(oacc[nb][1] * inv0) };
        *(float2*)(o0 + nb * 8 + 2 * tig) = a;
        float2 c = { rna_tf32(oacc[nb][2] * inv1), rna_tf32(oacc[nb][3] * inv1) };
        *(float2*)(o1 + nb * 8 + 2 * tig) = c;
    }
}

// ---------------------------------------------------------------------------
// Launch
// ---------------------------------------------------------------------------
extern "C" void kernel_launch(void* const* d_in, const int* in_sizes, int n_in,
                              void* d_out, int out_size)
{
    const float* hidden = (const float*)d_in[0];   // [B,S,D]
    const float* wqkv   = (const float*)d_in[1];   // [D, 3D]
    const float* bqkv   = (const float*)d_in[2];   // [3D]
    const float* wproj  = (const float*)d_in[3];   // [D, D]
    const float* bproj  = (const float*)d_in[4];   // [D]
    float* out = (float*)d_out;                    // [B,S,D]

    void *qkv_p, *attn_p, *hr_p, *w1_p, *w2_p;
    cudaGetSymbolAddress(&qkv_p, g_qkv);
    cudaGetSymbolAddress(&attn_p, g_attn);
    cudaGetSymbolAddress(&hr_p, g_hid_r);
    cudaGetSymbolAddress(&w1_p, g_w1_r);
    cudaGetSymbolAddress(&w2_p, g_w2_r);
    float* qkv  = (float*)qkv_p;
    float* attn = (float*)attn_p;
    float* hid_r = (float*)hr_p;
    float* w1_r  = (float*)w1_p;
    float* w2_r  = (float*)w2_p;

    const int GEMM_SMEM = 19776 * 4;   // 79104 B
    const int ATTN_SMEM = 3 * 64 * 68 * 4;  // 52224 B
    cudaFuncSetAttribute(tf32_gemm_pipe_kernel,
                         cudaFuncAttributeMaxDynamicSharedMemorySize, GEMM_SMEM);
    cudaFuncSetAttribute(attn_tc_kernel,
                         cudaFuncAttributeMaxDynamicSharedMemorySize, ATTN_SMEM);

    // 0) Round GEMM operands to tf32-representable fp32
    round_tf32_kernel<<<4096, 256>>>(hidden, hid_r, NTOK * DD / 4);
    round_tf32_kernel<<<3072, 256>>>(wqkv, w1_r, DD * D3 / 4);
    round_tf32_kernel<<<1024, 256>>>(wproj, w2_r, DD * DD / 4);

    // 1) QKV projection
    {
        dim3 grid(D3 / 128, NTOK / 128);   // 24 x 32
        tf32_gemm_pipe_kernel<<<grid, 256, GEMM_SMEM>>>(
            NTOK, D3, DD, hid_r, w1_r, bqkv, qkv);
    }

    // 2) Tensor-core causal flash attention
    {
        dim3 grid(QT, BB * HH);            // 32 x 32
        attn_tc_kernel<<<grid, 128, ATTN_SMEM>>>(qkv, attn);
    }

    // 3) Output projection
    {
        dim3 grid(DD / 128, NTOK / 128);   // 8 x 32
        tf32_gemm_pipe_kernel<<<grid, 256, GEMM_SMEM>>>(
            NTOK, DD, DD, attn, w2_r, bproj, out);
    }
}

// round 8
// speedup vs baseline: 4.3419x; 1.8355x over previous
#include <cuda_runtime.h>
#include <cstdint>

// Problem constants
#define BB 2
#define SS 2048
#define DD 1024
#define HH 16
#define HD 64
#define NTOK (BB * SS)          // 4096
#define D3  (3 * DD)            // 3072
#define GK  1024                // K of both GEMMs
#define QT  (SS / 64)           // 32 q-tiles per (b,h)
#define LOG2E 1.4426950408889634f

// Scratch (device globals: allocation-free, graph-capture safe)
__device__ float g_qkv[(size_t)NTOK * D3];    // [4096, 3072]
__device__ float g_attn[(size_t)NTOK * DD];   // [4096, 1024] (tf32-rounded)
__device__ float g_hid_r[(size_t)NTOK * DD];  // tf32-rounded hidden
__device__ float g_w1t[(size_t)D3 * DD];      // wqkv^T [3072,1024], rounded
__device__ float g_w2t[(size_t)DD * DD];      // wproj^T [1024,1024], rounded

__device__ __forceinline__ float rna_tf32(float x) {
    unsigned u; asm("cvt.rna.tf32.f32 %0, %1;" : "=r"(u) : "f"(x));
    return __uint_as_float(u);
}
__device__ __forceinline__ float ex2(float x) {
    float r; asm("ex2.approx.f32 %0, %1;" : "=f"(r) : "f"(x)); return r;
}
__device__ __forceinline__ void mma_tf32(float c[4], const unsigned a[4],
                                         const unsigned b0, const unsigned b1) {
    asm volatile(
        "mma.sync.aligned.m16n8k8.row.col.f32.tf32.tf32.f32 "
        "{%0,%1,%2,%3}, {%4,%5,%6,%7}, {%8,%9}, {%0,%1,%2,%3};"
        : "+f"(c[0]), "+f"(c[1]), "+f"(c[2]), "+f"(c[3])
        : "r"(a[0]), "r"(a[1]), "r"(a[2]), "r"(a[3]), "r"(b0), "r"(b1));
}
// ldmatrix m8n8.x4: lane i supplies the address of row i%8 of matrix i/8;
// thread t receives 32-bit word t%4 of row t/4 of each matrix.
// For 32-bit data each 8x8-b16 "matrix" is 8 rows x 4 tf32 (16B per row).
__device__ __forceinline__ void ldsm4(unsigned r[4], uint32_t addr) {
    asm volatile("ldmatrix.sync.aligned.m8n8.x4.shared.b16 {%0,%1,%2,%3}, [%4];"
        : "=r"(r[0]), "=r"(r[1]), "=r"(r[2]), "=r"(r[3]) : "r"(addr));
}

#define CPA16(dst, src) \
    asm volatile("cp.async.cg.shared.global [%0], [%1], 16;" :: "r"(dst), "l"(src))

__device__ __forceinline__ uint32_t smem_u32(const void* p) {
    uint32_t a;
    asm("{ .reg .u64 t; cvta.to.shared.u64 t, %1; cvt.u32.u64 %0, t; }"
        : "=r"(a) : "l"(p));
    return a;
}

// ---------------------------------------------------------------------------
// Prepass: elementwise tf32 round (hidden) and transpose+round (weights)
// ---------------------------------------------------------------------------
__global__ __launch_bounds__(256) void round_tf32_kernel(
    const float* __restrict__ in, float* __restrict__ out, int n4)
{
    int i = blockIdx.x * blockDim.x + threadIdx.x;
    if (i < n4) {
        float4 v = ((const float4*)in)[i];
        v.x = rna_tf32(v.x); v.y = rna_tf32(v.y);
        v.z = rna_tf32(v.z); v.w = rna_tf32(v.w);
        ((float4*)out)[i] = v;
    }
}

__global__ __launch_bounds__(256) void transpose_round_kernel(
    const float* __restrict__ in, float* __restrict__ out, int R, int C)
{
    __shared__ float t[32][33];
    int bx = blockIdx.x * 32, by = blockIdx.y * 32;
    int tx = threadIdx.x, ty = threadIdx.y;
    #pragma unroll
    for (int i = 0; i < 32; i += 8)
        t[ty + i][tx] = rna_tf32(in[(size_t)(by + ty + i) * C + bx + tx]);
    __syncthreads();
    #pragma unroll
    for (int i = 0; i < 32; i += 8)
        out[(size_t)(bx + ty + i) * R + by + tx] = t[tx][ty + i];
}

// ---------------------------------------------------------------------------
// TF32 mma.sync GEMM with ldmatrix fragment loads.
// C[M,N] = A[M,GK] @ Bt[N,GK]^T + bias[N].
// CTA 128x128, BK=32, 3-stage cp.async, 256 thr = 8 warps x (32m x 64n).
// smem rows: 32 floats = 128B, SW128 XOR swizzle (granule ^= row&7).
// ---------------------------------------------------------------------------
#define NCH 32                 // GK/32 chunks
#define STAGE_BYTES 32768u     // A 16KB + B 16KB
#define GEMM_SMEM (3 * 32768)

__device__ __forceinline__ void gemm_load_stage(
    uint32_t base, int st, int k0, int tid,
    const float* __restrict__ A, const float* __restrict__ Bt,
    int brow, int bcol)
{
    uint32_t aB = base + (uint32_t)st * STAGE_BYTES;
    uint32_t bB = aB + 16384u;
    #pragma unroll
    for (int it = 0; it < 8; it++) {
        int c = (tid + it * 256) & 1023;
        bool isA = it < 4;
        int row = c >> 3, g = c & 7;
        const float* gp = isA
            ? (A  + (size_t)(brow + row) * GK + k0 + g * 4)
            : (Bt + (size_t)(bcol + row) * GK + k0 + g * 4);
        uint32_t off = (uint32_t)(row * 128 + ((g ^ (row & 7)) << 4));
        CPA16((isA ? aB : bB) + off, gp);
    }
    asm volatile("cp.async.commit_group;" ::: "memory");
}

__global__ __launch_bounds__(256, 2) void mma_gemm_kernel(
    int N,
    const float* __restrict__ A,
    const float* __restrict__ Bt,
    const float* __restrict__ bias,
    float* __restrict__ C)
{
    extern __shared__ float sm[];
    const uint32_t base = smem_u32(sm);

    const int tid = threadIdx.x;
    const int wid = tid >> 5, lane = tid & 31;
    const int wm = wid & 3, wn = wid >> 2;
    const int brow = blockIdx.y * 128;
    const int bcol = blockIdx.x * 128;
    const int gid = lane >> 2, tig = lane & 3;

    // ldmatrix per-thread row/granule components
    const int rA = lane & 15;                       // A frag: mats 0,1 rows 0-15; 2,3 repeat
    const int hA = lane >> 4;                       //  granule half (0: k 0-3, 1: k 4-7)
    const int rB = (lane & 7) + ((lane >> 1) & 8);  // B pair: rows 0-7, 0-7, 8-15, 8-15
    const int hB = (lane >> 3) & 1;                 //  granule half alternates per mat

    float acc[2][8][4];
    #pragma unroll
    for (int i = 0; i < 2; i++)
        #pragma unroll
        for (int j = 0; j < 8; j++)
            #pragma unroll
            for (int e = 0; e < 4; e++) acc[i][j][e] = 0.f;

    gemm_load_stage(base, 0, 0,  tid, A, Bt, brow, bcol);
    gemm_load_stage(base, 1, 32, tid, A, Bt, brow, bcol);

    for (int i = 0; i < NCH; i++) {
        int st = i % 3;
        if (i < NCH - 1) asm volatile("cp.async.wait_group 1;" ::: "memory");
        else             asm volatile("cp.async.wait_group 0;" ::: "memory");
        __syncthreads();
        if (i + 2 < NCH)
            gemm_load_stage(base, (i + 2) % 3, (i + 2) * 32, tid, A, Bt, brow, bcol);

        uint32_t aBase = base + (uint32_t)st * STAGE_BYTES;
        uint32_t bBase = aBase + 16384u;

        #pragma unroll
        for (int kb = 0; kb < 4; kb++) {
            unsigned af[2][4];
            #pragma unroll
            for (int i2 = 0; i2 < 2; i2++) {
                int row = wm * 32 + i2 * 16 + rA;
                int g = (kb * 2 + hA) ^ (row & 7);
                ldsm4(af[i2], aBase + row * 128 + (g << 4));
            }
            unsigned bf[4][4];
            #pragma unroll
            for (int p = 0; p < 4; p++) {
                int row = wn * 64 + p * 16 + rB;
                int g = (kb * 2 + hB) ^ (row & 7);
                ldsm4(bf[p], bBase + row * 128 + (g << 4));
            }
            #pragma unroll
            for (int p = 0; p < 4; p++)
                #pragma unroll
                for (int i2 = 0; i2 < 2; i2++) {
                    mma_tf32(acc[i2][2 * p],     af[i2], bf[p][0], bf[p][1]);
                    mma_tf32(acc[i2][2 * p + 1], af[i2], bf[p][2], bf[p][3]);
                }
        }
    }

    // Epilogue: bias + store (acc[i2][j] -> rows wm*32+i2*16+{gid,gid+8},
    // cols wn*64 + j*8 + 2*tig)
    #pragma unroll
    for (int i2 = 0; i2 < 2; i2++) {
        int row = brow + wm * 32 + i2 * 16 + gid;
        #pragma unroll
        for (int j = 0; j < 8; j++) {
            int col = bcol + wn * 64 + j * 8 + 2 * tig;
            float b0 = __ldg(bias + col), b1 = __ldg(bias + col + 1);
            float2 lo = { acc[i2][j][0] + b0, acc[i2][j][1] + b1 };
            float2 hi = { acc[i2][j][2] + b0, acc[i2][j][3] + b1 };
            *(float2*)(C + (size_t)row * N + col) = lo;
            *(float2*)(C + (size_t)(row + 8) * N + col) = hi;
        }
    }
}

// ---------------------------------------------------------------------------
// Tensor-core causal flash attention (tf32 mma.sync) with ldmatrix loads for
// Q frags, S-loop K frags and P reload. PV keeps scalar V loads.
// Block 128 thr (4 warps) = 64 q-rows of one (b,h); smem stride 68 floats.
// ---------------------------------------------------------------------------
__global__ __launch_bounds__(128) void attn_tc_kernel(
    const float* __restrict__ qkv, float* __restrict__ out)
{
    extern __shared__ float sm[];
    float* Ks = sm;
    float* Vs = sm + 64 * 68;
    float* Ps = sm + 2 * 64 * 68;
    const uint32_t ksb = smem_u32(Ks);
    const uint32_t psb = smem_u32(Ps);

    const int qt = (QT - 1) - blockIdx.x;     // heavy tiles first
    const int bh = blockIdx.y;
    const int b = bh >> 4, h = bh & 15;
    const int tid = threadIdx.x;
    const int w = tid >> 5, lane = tid & 31;
    const int gid = lane >> 2, tig = lane & 3;

    const int rA = lane & 15;
    const int hA = lane >> 4;
    const int rB = (lane & 7) + ((lane >> 1) & 8);
    const int hB = (lane >> 3) & 1;

    const int tok0 = b * SS + qt * 64;
    const float* qbase = qkv + (size_t)tok0 * D3 + h * HD;
    const int c4 = tid & 15, r0 = tid >> 4;

    // Stage Q (scaled by 1/8*log2e, tf32-rounded) into Ps
    {
        const float s = 0.125f * LOG2E;
        #pragma unroll
        for (int i = 0; i < 8; i++) {
            int row = r0 + i * 8;
            float4 v = *(const float4*)(qbase + (size_t)row * D3 + c4 * 4);
            v.x = rna_tf32(v.x * s); v.y = rna_tf32(v.y * s);
            v.z = rna_tf32(v.z * s); v.w = rna_tf32(v.w * s);
            *(float4*)(Ps + row * 68 + c4 * 4) = v;
        }
    }
    __syncthreads();

    // Q fragments via ldmatrix (A-frag: row = w*16 + rA, granule kb*2+hA)
    unsigned qf[8][4];
    const int rr = w * 16 + gid;
    #pragma unroll
    for (int kb = 0; kb < 8; kb++) {
        int row = w * 16 + rA;
        ldsm4(qf[kb], psb + (uint32_t)(row * 68 + (kb * 2 + hA) * 4) * 4);
    }

    float oacc[8][4];
    #pragma unroll
    for (int i = 0; i < 8; i++)
        #pragma unroll
        for (int j = 0; j < 4; j++) oacc[i][j] = 0.f;
    float m0 = -1e30f, m1 = -1e30f, l0 = 0.f, l1 = 0.f;

    const float* kvbase = qkv + (size_t)(b * SS) * D3 + DD + h * HD;

    for (int kt = 0; kt <= qt; kt++) {
        // Load + tf32-round K and V tiles
        {
            const float* kb_ = kvbase + (size_t)(kt * 64) * D3;
            #pragma unroll
            for (int i = 0; i < 8; i++) {
                int row = r0 + i * 8;
                float4 kv = *(const float4*)(kb_ + (size_t)row * D3 + c4 * 4);
                kv.x = rna_tf32(kv.x); kv.y = rna_tf32(kv.y);
                kv.z = rna_tf32(kv.z); kv.w = rna_tf32(kv.w);
                *(float4*)(Ks + row * 68 + c4 * 4) = kv;
                float4 vv = *(const float4*)(kb_ + (size_t)row * D3 + DD + c4 * 4);
                vv.x = rna_tf32(vv.x); vv.y = rna_tf32(vv.y);
                vv.z = rna_tf32(vv.z); vv.w = rna_tf32(vv.w);
                *(float4*)(Vs + row * 68 + c4 * 4) = vv;
            }
        }
        __syncthreads();

        // S = Q @ K^T : 4 key-pairs of 16, B frags via ldmatrix
        float sacc[8][4];
        #pragma unroll
        for (int i = 0; i < 8; i++)
            #pragma unroll
            for (int j = 0; j < 4; j++) sacc[i][j] = 0.f;
        #pragma unroll
        for (int p = 0; p < 4; p++) {
            int row = p * 16 + rB;
            #pragma unroll
            for (int kb = 0; kb < 8; kb++) {
                unsigned bf[4];
                ldsm4(bf, ksb + (uint32_t)(row * 68 + (kb * 2 + hB) * 4) * 4);
                mma_tf32(sacc[2 * p],     qf[kb], bf[0], bf[1]);
                mma_tf32(sacc[2 * p + 1], qf[kb], bf[2], bf[3]);
            }
        }

        // Causal mask (diagonal tile only)
        if (kt == qt) {
            #pragma unroll
            for (int nb = 0; nb < 8; nb++) {
                int c0 = nb * 8 + 2 * tig, c1 = c0 + 1;
                if (c0 > rr)     sacc[nb][0] = -1e30f;
                if (c1 > rr)     sacc[nb][1] = -1e30f;
                if (c0 > rr + 8) sacc[nb][2] = -1e30f;
                if (c1 > rr + 8) sacc[nb][3] = -1e30f;
            }
        }

        // Row max
        float mt0 = -1e30f, mt1 = -1e30f;
        #pragma unroll
        for (int nb = 0; nb < 8; nb++) {
            mt0 = fmaxf(mt0, fmaxf(sacc[nb][0], sacc[nb][1]));
            mt1 = fmaxf(mt1, fmaxf(sacc[nb][2], sacc[nb][3]));
        }
        mt0 = fmaxf(mt0, __shfl_xor_sync(0xffffffffu, mt0, 1));
        mt0 = fmaxf(mt0, __shfl_xor_sync(0xffffffffu, mt0, 2));
        mt1 = fmaxf(mt1, __shfl_xor_sync(0xffffffffu, mt1, 1));
        mt1 = fmaxf(mt1, __shfl_xor_sync(0xffffffffu, mt1, 2));

        float mn0 = fmaxf(m0, mt0), mn1 = fmaxf(m1, mt1);
        float corr0 = ex2(m0 - mn0), corr1 = ex2(m1 - mn1);
        m0 = mn0; m1 = mn1;

        // P = 2^(S - m), row sums
        float rs0 = 0.f, rs1 = 0.f;
        #pragma unroll
        for (int nb = 0; nb < 8; nb++) {
            sacc[nb][0] = ex2(sacc[nb][0] - m0);
            sacc[nb][1] = ex2(sacc[nb][1] - m0);
            sacc[nb][2] = ex2(sacc[nb][2] - m1);
            sacc[nb][3] = ex2(sacc[nb][3] - m1);
            rs0 += sacc[nb][0] + sacc[nb][1];
            rs1 += sacc[nb][2] + sacc[nb][3];
        }
        rs0 += __shfl_xor_sync(0xffffffffu, rs0, 1);
        rs0 += __shfl_xor_sync(0xffffffffu, rs0, 2);
        rs1 += __shfl_xor_sync(0xffffffffu, rs1, 1);
        rs1 += __shfl_xor_sync(0xffffffffu, rs1, 2);
        l0 = l0 * corr0 + rs0;
        l1 = l1 * corr1 + rs1;

        #pragma unroll
        for (int nb = 0; nb < 8; nb++) {
            oacc[nb][0] *= corr0; oacc[nb][1] *= corr0;
            oacc[nb][2] *= corr1; oacc[nb][3] *= corr1;
        }

        // Store P (tf32-rounded) to own warp strip of Ps
        #pragma unroll
        for (int nb = 0; nb < 8; nb++) {
            float2 p01 = { rna_tf32(sacc[nb][0]), rna_tf32(sacc[nb][1]) };
            *(float2*)(Ps + rr * 68 + nb * 8 + 2 * tig) = p01;
            float2 p23 = { rna_tf32(sacc[nb][2]), rna_tf32(sacc[nb][3]) };
            *(float2*)(Ps + (rr + 8) * 68 + nb * 8 + 2 * tig) = p23;
        }
        __syncwarp();

        // O += P @ V : P A-frags via ldmatrix, V scalar B loads
        #pragma unroll
        for (int kb = 0; kb < 8; kb++) {
            unsigned pf[4];
            int row = w * 16 + rA;
            ldsm4(pf, psb + (uint32_t)(row * 68 + (kb * 2 + hA) * 4) * 4);
            #pragma unroll
            for (int nb = 0; nb < 8; nb++) {
                unsigned bf0 = __float_as_uint(Vs[(kb * 8 + tig) * 68 + nb * 8 + gid]);
                unsigned bf1 = __float_as_uint(Vs[(kb * 8 + tig + 4) * 68 + nb * 8 + gid]);
                mma_tf32(oacc[nb], pf, bf0, bf1);
            }
        }
        __syncthreads();
    }

    // Epilogue: normalize, round to tf32 (feeds proj GEMM), store
    float inv0 = 1.f / l0, inv1 = 1.f / l1;
    float* o0 = out + (size_t)(tok0 + rr) * DD + h * HD;
    float* o1 = out + (size_t)(tok0 + rr + 8) * DD + h * HD;
    #pragma unroll
    for (int nb = 0; nb < 8; nb++) {
        float2 a = { rna_tf32(oacc[nb][0] * inv0), rna_tf32(oacc[nb][1] * inv0) };
        *(float2*)(o0 + nb * 8 + 2 * tig) = a;
        float2 c = { rna_tf32(oacc[nb][2] * inv1), rna_tf32(oacc[nb][3] * inv1) };
        *(float2*)(o1 + nb * 8 + 2 * tig) = c;
    }
}

// ---------------------------------------------------------------------------
// Launch
// ---------------------------------------------------------------------------
extern "C" void kernel_launch(void* const* d_in, const int* in_sizes, int n_in,
                              void* d_out, int out_size)
{
    const float* hidden = (const float*)d_in[0];   // [B,S,D]
    const float* wqkv   = (const float*)d_in[1];   // [D, 3D]
    const float* bqkv   = (const float*)d_in[2];   // [3D]
    const float* wproj  = (const float*)d_in[3];   // [D, D]
    const float* bproj  = (const float*)d_in[4];   // [D]
    float* out = (float*)d_out;                    // [B,S,D]

    void *qkv_p, *attn_p, *hr_p, *w1_p, *w2_p;
    cudaGetSymbolAddress(&qkv_p, g_qkv);
    cudaGetSymbolAddress(&attn_p, g_attn);
    cudaGetSymbolAddress(&hr_p, g_hid_r);
    cudaGetSymbolAddress(&w1_p, g_w1t);
    cudaGetSymbolAddress(&w2_p, g_w2t);
    float* qkv   = (float*)qkv_p;
    float* attn  = (float*)attn_p;
    float* hid_r = (float*)hr_p;
    float* w1t   = (float*)w1_p;
    float* w2t   = (float*)w2_p;

    const int ATTN_SMEM = 3 * 64 * 68 * 4;  // 52224 B
    cudaFuncSetAttribute(mma_gemm_kernel,
                         cudaFuncAttributeMaxDynamicSharedMemorySize, GEMM_SMEM);
    cudaFuncSetAttribute(attn_tc_kernel,
                         cudaFuncAttributeMaxDynamicSharedMemorySize, ATTN_SMEM);

    // 0) Prepass: round hidden; transpose+round weights to [N,K]
    round_tf32_kernel<<<4096, 256>>>(hidden, hid_r, NTOK * DD / 4);
    {
        dim3 blk(32, 8);
        dim3 g1(D3 / 32, DD / 32);
        transpose_round_kernel<<<g1, blk>>>(wqkv, w1t, DD, D3);
        dim3 g2(DD / 32, DD / 32);
        transpose_round_kernel<<<g2, blk>>>(wproj, w2t, DD, DD);
    }

    // 1) QKV projection
    {
        dim3 grid(D3 / 128, NTOK / 128);   // 24 x 32
        mma_gemm_kernel<<<grid, 256, GEMM_SMEM>>>(D3, hid_r, w1t, bqkv, qkv);
    }

    // 2) Tensor-core causal flash attention
    {
        dim3 grid(QT, BB * HH);            // 32 x 32
        attn_tc_kernel<<<grid, 128, ATTN_SMEM>>>(qkv, attn);
    }

    // 3) Output projection
    {
        dim3 grid(DD / 128, NTOK / 128);   // 8 x 32
        mma_gemm_kernel<<<grid, 256, GEMM_SMEM>>>(DD, attn, w2t, bproj, out);
    }
}